// round 13
// baseline (speedup 1.0000x reference)
#include <cuda_runtime.h>
#include <math.h>

// Problem constants (fixed by reference setup_inputs)
#define BB   2
#define TT   2048
#define SS   2048
#define DD   1024
#define HH   16
#define DK   64

// Scratch (allocation-free rule: __device__ globals)
__device__ float g_q[BB * TT * DD];     // (B*T, H*DK) q projected, pre-scaled
__device__ float g_k[BB * SS * DD];
__device__ float g_v[BB * SS * DD];
__device__ float g_attn[BB * TT * DD];  // attention output before Wo

__device__ __forceinline__ unsigned f2tf32(float f) {
    unsigned r;
    asm("cvt.rna.tf32.f32 %0, %1;" : "=r"(r) : "f"(f));
    return r;
}

// Split f into hi + lo, both tf32-representable (3-term fp32 emulation).
__device__ __forceinline__ void split_tf32(float f, unsigned& hi, unsigned& lo) {
    unsigned h = f2tf32(f);
    hi = h;
    lo = f2tf32(f - __uint_as_float(h));
}

__device__ __forceinline__ void mma_tf32(float* acc, const unsigned* a, const unsigned* b) {
    asm volatile(
        "mma.sync.aligned.m16n8k8.row.col.f32.tf32.tf32.f32 "
        "{%0,%1,%2,%3}, {%4,%5,%6,%7}, {%8,%9}, {%0,%1,%2,%3};"
        : "+f"(acc[0]), "+f"(acc[1]), "+f"(acc[2]), "+f"(acc[3])
        : "r"(a[0]), "r"(a[1]), "r"(a[2]), "r"(a[3]), "r"(b[0]), "r"(b[1]));
}

// ---------------------------------------------------------------------------
// Split-tf32 tensor-core GEMM body (fp32-accurate): C = alpha*(A@W + bias)
// acc += aL*bH + aH*bL + aH*bH  (residual ~u^2, i.e. ~fp32 accuracy)
// 128x128 block tile, BK=16, 256 threads = 8 warps (2x4), warp tile 64x32.
// Shared by the fused-QKV kernel and the output-projection kernel.
// ---------------------------------------------------------------------------
#define ASTRIDE 132
#define BSTRIDE 132

__device__ __forceinline__
void sgemm_body(const float* __restrict__ A, const float* __restrict__ W,
                const float* __restrict__ bias, float* __restrict__ C,
                float alpha, int M, int N, int K)
{
    __shared__ unsigned AsH[16][ASTRIDE];
    __shared__ unsigned AsL[16][ASTRIDE];
    __shared__ unsigned BsH[16][BSTRIDE];
    __shared__ unsigned BsL[16][BSTRIDE];

    const int tid    = threadIdx.x;
    const int lane   = tid & 31;
    const int warpid = tid >> 5;
    const int g      = lane >> 2;
    const int tig    = lane & 3;
    const int wm     = (warpid >> 2) * 64;
    const int wn     = (warpid & 3) * 32;

    const int m0 = blockIdx.y * 128;
    const int n0 = blockIdx.x * 128;

    const int arow = tid >> 1;
    const int ak4  = (tid & 1) * 4;
    const int bk   = tid >> 5;
    const int bn   = (tid & 31) * 4;

    const float* aRow  = &A[(m0 + arow) * K + ak4];
    const float* bBase = &W[bk * N + n0 + bn];

    float acc[4][4][4];
#pragma unroll
    for (int mt = 0; mt < 4; mt++)
#pragma unroll
        for (int nt = 0; nt < 4; nt++)
#pragma unroll
            for (int i = 0; i < 4; i++) acc[mt][nt][i] = 0.0f;

    float4 av0 = *(const float4*)(aRow);
    float4 av1 = *(const float4*)(aRow + 8);
    float4 bv0 = *(const float4*)(bBase);
    float4 bv1 = *(const float4*)(bBase + 8 * N);

    for (int k0 = 0; k0 < K; k0 += 16) {
        {
            float a[8] = {av0.x, av0.y, av0.z, av0.w, av1.x, av1.y, av1.z, av1.w};
#pragma unroll
            for (int i = 0; i < 4; i++) {
                unsigned h, l;
                split_tf32(a[i], h, l);
                AsH[ak4 + i][arow] = h;
                AsL[ak4 + i][arow] = l;
                split_tf32(a[i + 4], h, l);
                AsH[ak4 + 8 + i][arow] = h;
                AsL[ak4 + 8 + i][arow] = l;
            }
            float b0[4] = {bv0.x, bv0.y, bv0.z, bv0.w};
            float b1[4] = {bv1.x, bv1.y, bv1.z, bv1.w};
            uint4 h0, l0, h1, l1;
            split_tf32(b0[0], h0.x, l0.x); split_tf32(b0[1], h0.y, l0.y);
            split_tf32(b0[2], h0.z, l0.z); split_tf32(b0[3], h0.w, l0.w);
            split_tf32(b1[0], h1.x, l1.x); split_tf32(b1[1], h1.y, l1.y);
            split_tf32(b1[2], h1.z, l1.z); split_tf32(b1[3], h1.w, l1.w);
            *(uint4*)&BsH[bk][bn]     = h0;
            *(uint4*)&BsL[bk][bn]     = l0;
            *(uint4*)&BsH[bk + 8][bn] = h1;
            *(uint4*)&BsL[bk + 8][bn] = l1;
        }
        __syncthreads();

        if (k0 + 16 < K) {
            av0 = *(const float4*)(aRow + k0 + 16);
            av1 = *(const float4*)(aRow + k0 + 24);
            bv0 = *(const float4*)(bBase + (k0 + 16) * N);
            bv1 = *(const float4*)(bBase + (k0 + 24) * N);
        }

#pragma unroll
        for (int ks = 0; ks < 16; ks += 8) {
            unsigned aH[4][4], aL[4][4], bH[4][2], bL[4][2];
#pragma unroll
            for (int mt = 0; mt < 4; mt++) {
                int row = wm + mt * 16 + g;
                aH[mt][0] = AsH[ks + tig][row];
                aH[mt][1] = AsH[ks + tig][row + 8];
                aH[mt][2] = AsH[ks + tig + 4][row];
                aH[mt][3] = AsH[ks + tig + 4][row + 8];
                aL[mt][0] = AsL[ks + tig][row];
                aL[mt][1] = AsL[ks + tig][row + 8];
                aL[mt][2] = AsL[ks + tig + 4][row];
                aL[mt][3] = AsL[ks + tig + 4][row + 8];
            }
#pragma unroll
            for (int nt = 0; nt < 4; nt++) {
                int col = wn + nt * 8 + g;
                bH[nt][0] = BsH[ks + tig][col];
                bH[nt][1] = BsH[ks + tig + 4][col];
                bL[nt][0] = BsL[ks + tig][col];
                bL[nt][1] = BsL[ks + tig + 4][col];
            }
#pragma unroll
            for (int mt = 0; mt < 4; mt++)
#pragma unroll
                for (int nt = 0; nt < 4; nt++) {
                    mma_tf32(acc[mt][nt], aL[mt], bH[nt]);
                    mma_tf32(acc[mt][nt], aH[mt], bL[nt]);
                    mma_tf32(acc[mt][nt], aH[mt], bH[nt]);
                }
        }
        __syncthreads();
    }

#pragma unroll
    for (int nt = 0; nt < 4; nt++) {
        int col = n0 + wn + nt * 8 + 2 * tig;
        float b0 = bias[col];
        float b1 = bias[col + 1];
#pragma unroll
        for (int mt = 0; mt < 4; mt++) {
            int row0 = m0 + wm + mt * 16 + g;
            float2 v0 = make_float2((acc[mt][nt][0] + b0) * alpha,
                                    (acc[mt][nt][1] + b1) * alpha);
            float2 v1 = make_float2((acc[mt][nt][2] + b0) * alpha,
                                    (acc[mt][nt][3] + b1) * alpha);
            *(float2*)&C[row0 * N + col]       = v0;
            *(float2*)&C[(row0 + 8) * N + col] = v1;
        }
    }
}

// Fused Q/K/V projection: blockIdx.z in {0,1,2} selects the GEMM.
// One launch of 768 CTAs instead of three 256-CTA launches (tail amortized).
__global__ __launch_bounds__(256)
void qkv_proj(const float* __restrict__ query, const float* __restrict__ key,
              const float* __restrict__ value,
              const float* __restrict__ Wq, const float* __restrict__ Wk,
              const float* __restrict__ Wv,
              const float* __restrict__ bq, const float* __restrict__ bk,
              const float* __restrict__ bv,
              float* __restrict__ oq, float* __restrict__ ok,
              float* __restrict__ ov, float qscale)
{
    const int z = blockIdx.z;
    const float* A    = (z == 0) ? query : (z == 1) ? key : value;
    const float* W    = (z == 0) ? Wq    : (z == 1) ? Wk  : Wv;
    const float* bias = (z == 0) ? bq    : (z == 1) ? bk  : bv;
    float*       C    = (z == 0) ? oq    : (z == 1) ? ok  : ov;
    float alpha       = (z == 0) ? qscale : 1.0f;
    sgemm_body(A, W, bias, C, alpha, BB * TT, DD, DD);
}

// Output projection (single GEMM).
__global__ __launch_bounds__(256)
void out_proj(const float* __restrict__ A, const float* __restrict__ W,
              const float* __restrict__ bias, float* __restrict__ C)
{
    sgemm_body(A, W, bias, C, 1.0f, BB * TT, DD, DD);
}

// ---------------------------------------------------------------------------
// Flash attention with split-tf32 mma (fp32-accurate).
// Per CTA: (b, h, 128-query tile). 8 warps; warp w owns q rows [w*16, w*16+16)
// and ALL keys -> softmax is warp-local. Stream over S in 64-key tiles.
// K and V are split hi/lo ONCE at tile-load time and stored INTERLEAVED as
// uint2 {hi,lo}, so each inner-loop fragment fetch is a single LDS.64.
// Q fragments register-resident, pre-split. P split at read (warp-local).
// smem: Ks2/Vs2 [64][68] uint2, Ps [128][68] float.  (~102 KB -> 2 CTAs/SM)
// ---------------------------------------------------------------------------
#define Bb_R 128
#define Bb_C 64
#define SSTR 68
#define ATTN_SMEM ((4 * Bb_C * SSTR + Bb_R * SSTR) * 4)

__global__ __launch_bounds__(256)
void attn_mma(const float* __restrict__ q, const float* __restrict__ k,
              const float* __restrict__ v, float* __restrict__ o)
{
    extern __shared__ unsigned smu[];
    uint2* Ks2 = (uint2*)smu;                 // [64][SSTR] (key, dk) {hi,lo}
    uint2* Vs2 = Ks2 + Bb_C * SSTR;           // [64][SSTR] (key, dk) {hi,lo}
    float* Ps  = (float*)(Vs2 + Bb_C * SSTR); // [128][SSTR] (qrow, key)

    const int tid  = threadIdx.x;
    const int lane = tid & 31;
    const int w    = tid >> 5;
    const int g    = lane >> 2;
    const int tig  = lane & 3;
    const int b    = blockIdx.z;
    const int h    = blockIdx.y;
    const int t0   = blockIdx.x * Bb_R;
    const int r0   = w * 16 + g;       // q row (within tile) for a0/a2,c0/c1
    const int r1   = r0 + 8;           // for a1/a3,c2/c3

    // ---- Load Q fragments once, pre-split (q already scaled by 1/sqrt(DK))
    unsigned QH[8][4], QL[8][4];
    {
        const float* qb = q + (size_t)(b * TT + t0) * DD + h * DK;
#pragma unroll
        for (int ks = 0; ks < 8; ks++) {
            split_tf32(qb[r0 * DD + ks * 8 + tig],     QH[ks][0], QL[ks][0]);
            split_tf32(qb[r1 * DD + ks * 8 + tig],     QH[ks][1], QL[ks][1]);
            split_tf32(qb[r0 * DD + ks * 8 + tig + 4], QH[ks][2], QL[ks][2]);
            split_tf32(qb[r1 * DD + ks * 8 + tig + 4], QH[ks][3], QL[ks][3]);
        }
    }

    float O[8][4];
#pragma unroll
    for (int nt = 0; nt < 8; nt++)
#pragma unroll
        for (int i = 0; i < 4; i++) O[nt][i] = 0.0f;
    float m0_ = -INFINITY, m1_ = -INFINITY, l0_ = 0.0f, l1_ = 0.0f;

    const float* kb = k + (size_t)b * SS * DD + h * DK;
    const float* vb = v + (size_t)b * SS * DD + h * DK;

    for (int s0 = 0; s0 < SS; s0 += Bb_C) {
        __syncthreads();   // prior iter's PV reads of Ps/Vs done

        // ---- Load K,V tiles; split hi/lo once, store interleaved uint2
#pragma unroll
        for (int u = 0; u < 4; u++) {
            int idx = tid + u * 256;       // 0..1023
            int row = idx >> 4;            // 0..63
            int c4  = (idx & 15) * 4;      // 0..60
            float4 kv = *(const float4*)&kb[(size_t)(s0 + row) * DD + c4];
            float4 vv = *(const float4*)&vb[(size_t)(s0 + row) * DD + c4];
            uint4 kh, kl, vh, vl;
            split_tf32(kv.x, kh.x, kl.x); split_tf32(kv.y, kh.y, kl.y);
            split_tf32(kv.z, kh.z, kl.z); split_tf32(kv.w, kh.w, kl.w);
            split_tf32(vv.x, vh.x, vl.x); split_tf32(vv.y, vh.y, vl.y);
            split_tf32(vv.z, vh.z, vl.z); split_tf32(vv.w, vh.w, vl.w);
            *(uint4*)&Ks2[row * SSTR + c4]     = make_uint4(kh.x, kl.x, kh.y, kl.y);
            *(uint4*)&Ks2[row * SSTR + c4 + 2] = make_uint4(kh.z, kl.z, kh.w, kl.w);
            *(uint4*)&Vs2[row * SSTR + c4]     = make_uint4(vh.x, vl.x, vh.y, vl.y);
            *(uint4*)&Vs2[row * SSTR + c4 + 2] = make_uint4(vh.z, vl.z, vh.w, vl.w);
        }
        __syncthreads();

        // ---- Scores S = Q K^T (split-3). B-frag b0=(k=tig,n=g): Ks[n][k].
        float S[8][4];
#pragma unroll
        for (int nt = 0; nt < 8; nt++)
#pragma unroll
            for (int i = 0; i < 4; i++) S[nt][i] = 0.0f;

#pragma unroll
        for (int ks = 0; ks < 8; ks++) {
#pragma unroll
            for (int nt = 0; nt < 8; nt++) {
                int i0 = (nt * 8 + g) * SSTR + ks * 8 + tig;
                uint2 p0 = Ks2[i0];          // {hi, lo} one LDS.64
                uint2 p1 = Ks2[i0 + 4];
                unsigned bH[2] = {p0.x, p1.x};
                unsigned bL[2] = {p0.y, p1.y};
                mma_tf32(S[nt], QL[ks], bH);
                mma_tf32(S[nt], QH[ks], bL);
                mma_tf32(S[nt], QH[ks], bH);
            }
        }

        // ---- Online softmax (warp-local; rows r0 and r1)
        float mx0 = -INFINITY, mx1 = -INFINITY;
#pragma unroll
        for (int nt = 0; nt < 8; nt++) {
            mx0 = fmaxf(mx0, fmaxf(S[nt][0], S[nt][1]));
            mx1 = fmaxf(mx1, fmaxf(S[nt][2], S[nt][3]));
        }
        mx0 = fmaxf(mx0, __shfl_xor_sync(0xffffffffu, mx0, 1));
        mx0 = fmaxf(mx0, __shfl_xor_sync(0xffffffffu, mx0, 2));
        mx1 = fmaxf(mx1, __shfl_xor_sync(0xffffffffu, mx1, 1));
        mx1 = fmaxf(mx1, __shfl_xor_sync(0xffffffffu, mx1, 2));

        float mn0 = fmaxf(m0_, mx0);
        float mn1 = fmaxf(m1_, mx1);
        float rs0 = 0.0f, rs1 = 0.0f;
#pragma unroll
        for (int nt = 0; nt < 8; nt++) {
            S[nt][0] = __expf(S[nt][0] - mn0);
            S[nt][1] = __expf(S[nt][1] - mn0);
            S[nt][2] = __expf(S[nt][2] - mn1);
            S[nt][3] = __expf(S[nt][3] - mn1);
            rs0 += S[nt][0] + S[nt][1];
            rs1 += S[nt][2] + S[nt][3];
        }
        rs0 += __shfl_xor_sync(0xffffffffu, rs0, 1);
        rs0 += __shfl_xor_sync(0xffffffffu, rs0, 2);
        rs1 += __shfl_xor_sync(0xffffffffu, rs1, 1);
        rs1 += __shfl_xor_sync(0xffffffffu, rs1, 2);

        float al0 = __expf(m0_ - mn0);
        float al1 = __expf(m1_ - mn1);
        l0_ = l0_ * al0 + rs0;  m0_ = mn0;
        l1_ = l1_ * al1 + rs1;  m1_ = mn1;
#pragma unroll
        for (int nt = 0; nt < 8; nt++) {
            O[nt][0] *= al0;  O[nt][1] *= al0;
            O[nt][2] *= al1;  O[nt][3] *= al1;
        }

        // ---- Store P (C-frag layout: cols nt*8 + 2*tig)
#pragma unroll
        for (int nt = 0; nt < 8; nt++) {
            *(float2*)&Ps[r0 * SSTR + nt * 8 + 2 * tig] = make_float2(S[nt][0], S[nt][1]);
            *(float2*)&Ps[r1 * SSTR + nt * 8 + 2 * tig] = make_float2(S[nt][2], S[nt][3]);
        }
        __syncthreads();

        // ---- O += P @ V (split-3). A from Ps (split at read), B from Vs2.
#pragma unroll
        for (int ks = 0; ks < 8; ks++) {
            unsigned aH[4], aL[4];
            split_tf32(Ps[r0 * SSTR + ks * 8 + tig],     aH[0], aL[0]);
            split_tf32(Ps[r1 * SSTR + ks * 8 + tig],     aH[1], aL[1]);
            split_tf32(Ps[r0 * SSTR + ks * 8 + tig + 4], aH[2], aL[2]);
            split_tf32(Ps[r1 * SSTR + ks * 8 + tig + 4], aH[3], aL[3]);
#pragma unroll
            for (int nt = 0; nt < 8; nt++) {
                uint2 p0 = Vs2[(ks * 8 + tig) * SSTR + nt * 8 + g];
                uint2 p1 = Vs2[(ks * 8 + tig + 4) * SSTR + nt * 8 + g];
                unsigned bH[2] = {p0.x, p1.x};
                unsigned bL[2] = {p0.y, p1.y};
                mma_tf32(O[nt], aL, bH);
                mma_tf32(O[nt], aH, bL);
                mma_tf32(O[nt], aH, bH);
            }
        }
    }

    // ---- Normalize and store
    float inv0 = 1.0f / l0_;
    float inv1 = 1.0f / l1_;
    float* ob = o + (size_t)(b * TT + t0) * DD + h * DK;
#pragma unroll
    for (int nt = 0; nt < 8; nt++) {
        *(float2*)&ob[r0 * DD + nt * 8 + 2 * tig] =
            make_float2(O[nt][0] * inv0, O[nt][1] * inv0);
        *(float2*)&ob[r1 * DD + nt * 8 + 2 * tig] =
            make_float2(O[nt][2] * inv1, O[nt][3] * inv1);
    }
}

// ---------------------------------------------------------------------------
// Launch.  Input order: query, value, key, Wq, bq, Wk, bk, Wv, bv, Wo, bo
// ---------------------------------------------------------------------------
extern "C" void kernel_launch(void* const* d_in, const int* in_sizes, int n_in,
                              void* d_out, int out_size)
{
    const float* query = (const float*)d_in[0];
    const float* value = (const float*)d_in[1];
    const float* key   = (const float*)d_in[2];
    const float* Wq    = (const float*)d_in[3];
    const float* bq    = (const float*)d_in[4];
    const float* Wk    = (const float*)d_in[5];
    const float* bk    = (const float*)d_in[6];
    const float* Wv    = (const float*)d_in[7];
    const float* bv    = (const float*)d_in[8];
    const float* Wo    = (const float*)d_in[9];
    const float* bo    = (const float*)d_in[10];
    float* out = (float*)d_out;

    float* dq; cudaGetSymbolAddress((void**)&dq, g_q);
    float* dk; cudaGetSymbolAddress((void**)&dk, g_k);
    float* dv; cudaGetSymbolAddress((void**)&dv, g_v);
    float* da; cudaGetSymbolAddress((void**)&da, g_attn);

    cudaFuncSetAttribute(attn_mma, cudaFuncAttributeMaxDynamicSharedMemorySize,
                         ATTN_SMEM);

    const float qscale = 0.125f;  // 1/sqrt(DK=64)
    dim3 gblk(256);

    // Fused Q/K/V projections: one 768-CTA launch (z selects the GEMM)
    dim3 qkvgrid(DD / 128, (BB * TT) / 128, 3);
    qkv_proj<<<qkvgrid, gblk>>>(query, key, value, Wq, Wk, Wv, bq, bk, bv,
                                dq, dk, dv, qscale);

    // Attention
    dim3 agrid(TT / Bb_R, HH, BB);
    attn_mma<<<agrid, 256, ATTN_SMEM>>>(dq, dk, dv, da);

    // Output projection
    dim3 ogrid(DD / 128, (BB * TT) / 128);
    out_proj<<<ogrid, gblk>>>(da, Wo, bo, out);
}

// round 14
// speedup vs baseline: 1.0645x; 1.0645x over previous
#include <cuda_runtime.h>
#include <math.h>

// Problem constants (fixed by reference setup_inputs)
#define BB   2
#define TT   2048
#define SS   2048
#define DD   1024
#define HH   16
#define DK   64

// Scratch (allocation-free rule: __device__ globals)
__device__ float g_q[BB * TT * DD];     // (B*T, H*DK) q projected, pre-scaled
__device__ float g_k[BB * SS * DD];
__device__ float g_v[BB * SS * DD];
__device__ float g_attn[BB * TT * DD];  // attention output before Wo

__device__ __forceinline__ unsigned f2tf32(float f) {
    unsigned r;
    asm("cvt.rna.tf32.f32 %0, %1;" : "=r"(r) : "f"(f));
    return r;
}

// Split f into hi + lo, both tf32-representable (3-term fp32 emulation).
__device__ __forceinline__ void split_tf32(float f, unsigned& hi, unsigned& lo) {
    unsigned h = f2tf32(f);
    hi = h;
    lo = f2tf32(f - __uint_as_float(h));
}

__device__ __forceinline__ void mma_tf32(float* acc, const unsigned* a, const unsigned* b) {
    asm volatile(
        "mma.sync.aligned.m16n8k8.row.col.f32.tf32.tf32.f32 "
        "{%0,%1,%2,%3}, {%4,%5,%6,%7}, {%8,%9}, {%0,%1,%2,%3};"
        : "+f"(acc[0]), "+f"(acc[1]), "+f"(acc[2]), "+f"(acc[3])
        : "r"(a[0]), "r"(a[1]), "r"(a[2]), "r"(a[3]), "r"(b[0]), "r"(b[1]));
}

// ---------------------------------------------------------------------------
// Split-tf32 tensor-core GEMM body, 2-stage double-buffered (fp32-accurate):
// C = alpha*(A@W + bias);  acc += aL*bH + aH*bL + aH*bH.
// 128x128 block tile, BK=16, 256 threads = 8 warps (2x4), warp tile 64x32.
// Dynamic smem: 2 stages x {AsH,AsL,BsH,BsL}[16][132]. ONE sync per K-tile:
// store of tile i+1 overlaps (cross-warp) with mma of tile i.
// ---------------------------------------------------------------------------
#define GEMM_STAGE (16 * 132)                     // u32 per array per stage
#define GEMM_SMEM  (2 * 4 * GEMM_STAGE * 4)       // 67584 bytes

__device__ __forceinline__
void gemm_store_stage(unsigned* AsH, unsigned* AsL, unsigned* BsH, unsigned* BsL,
                      int s, float4 av0, float4 av1, float4 bv0, float4 bv1,
                      int arow, int ak4, int bk, int bn)
{
    unsigned* aH = AsH + s * GEMM_STAGE;
    unsigned* aL = AsL + s * GEMM_STAGE;
    unsigned* bH = BsH + s * GEMM_STAGE;
    unsigned* bL = BsL + s * GEMM_STAGE;
    float a[8] = {av0.x, av0.y, av0.z, av0.w, av1.x, av1.y, av1.z, av1.w};
#pragma unroll
    for (int i = 0; i < 4; i++) {
        unsigned h, l;
        split_tf32(a[i], h, l);
        aH[(ak4 + i) * 132 + arow] = h;
        aL[(ak4 + i) * 132 + arow] = l;
        split_tf32(a[i + 4], h, l);
        aH[(ak4 + 8 + i) * 132 + arow] = h;
        aL[(ak4 + 8 + i) * 132 + arow] = l;
    }
    uint4 h0, l0, h1, l1;
    split_tf32(bv0.x, h0.x, l0.x); split_tf32(bv0.y, h0.y, l0.y);
    split_tf32(bv0.z, h0.z, l0.z); split_tf32(bv0.w, h0.w, l0.w);
    split_tf32(bv1.x, h1.x, l1.x); split_tf32(bv1.y, h1.y, l1.y);
    split_tf32(bv1.z, h1.z, l1.z); split_tf32(bv1.w, h1.w, l1.w);
    *(uint4*)&bH[bk * 132 + bn]       = h0;
    *(uint4*)&bL[bk * 132 + bn]       = l0;
    *(uint4*)&bH[(bk + 8) * 132 + bn] = h1;
    *(uint4*)&bL[(bk + 8) * 132 + bn] = l1;
}

__device__ __forceinline__
void sgemm_body(const float* __restrict__ A, const float* __restrict__ W,
                const float* __restrict__ bias, float* __restrict__ C,
                float alpha, int M, int N, int K)
{
    extern __shared__ unsigned gsm[];
    unsigned* AsH = gsm;                     // [2][16][132]
    unsigned* AsL = gsm + 2 * GEMM_STAGE;
    unsigned* BsH = gsm + 4 * GEMM_STAGE;
    unsigned* BsL = gsm + 6 * GEMM_STAGE;

    const int tid    = threadIdx.x;
    const int lane   = tid & 31;
    const int warpid = tid >> 5;
    const int g      = lane >> 2;
    const int tig    = lane & 3;
    const int wm     = (warpid >> 2) * 64;
    const int wn     = (warpid & 3) * 32;

    const int m0 = blockIdx.y * 128;
    const int n0 = blockIdx.x * 128;

    const int arow = tid >> 1;
    const int ak4  = (tid & 1) * 4;
    const int bk   = tid >> 5;
    const int bn   = (tid & 31) * 4;

    const float* aRow  = &A[(m0 + arow) * K + ak4];
    const float* bBase = &W[bk * N + n0 + bn];

    float acc[4][4][4];
#pragma unroll
    for (int mt = 0; mt < 4; mt++)
#pragma unroll
        for (int nt = 0; nt < 4; nt++)
#pragma unroll
            for (int i = 0; i < 4; i++) acc[mt][nt][i] = 0.0f;

    // prologue: tile 0 -> stage 0
    float4 av0 = *(const float4*)(aRow);
    float4 av1 = *(const float4*)(aRow + 8);
    float4 bv0 = *(const float4*)(bBase);
    float4 bv1 = *(const float4*)(bBase + 8 * N);
    gemm_store_stage(AsH, AsL, BsH, BsL, 0, av0, av1, bv0, bv1, arow, ak4, bk, bn);
    __syncthreads();

    const int ntiles = K / 16;
    for (int i = 0; i < ntiles; i++) {
        const int cur  = i & 1;
        const bool more = (i + 1 < ntiles);
        if (more) {
            const int k0 = (i + 1) * 16;
            av0 = *(const float4*)(aRow + k0);
            av1 = *(const float4*)(aRow + k0 + 8);
            bv0 = *(const float4*)(bBase + k0 * N);
            bv1 = *(const float4*)(bBase + (k0 + 8) * N);
        }

        const unsigned* aHs = AsH + cur * GEMM_STAGE;
        const unsigned* aLs = AsL + cur * GEMM_STAGE;
        const unsigned* bHs = BsH + cur * GEMM_STAGE;
        const unsigned* bLs = BsL + cur * GEMM_STAGE;

#pragma unroll
        for (int ks = 0; ks < 16; ks += 8) {
            unsigned aH[4][4], aL[4][4], bH[4][2], bL[4][2];
#pragma unroll
            for (int mt = 0; mt < 4; mt++) {
                int row = wm + mt * 16 + g;
                aH[mt][0] = aHs[(ks + tig) * 132 + row];
                aH[mt][1] = aHs[(ks + tig) * 132 + row + 8];
                aH[mt][2] = aHs[(ks + tig + 4) * 132 + row];
                aH[mt][3] = aHs[(ks + tig + 4) * 132 + row + 8];
                aL[mt][0] = aLs[(ks + tig) * 132 + row];
                aL[mt][1] = aLs[(ks + tig) * 132 + row + 8];
                aL[mt][2] = aLs[(ks + tig + 4) * 132 + row];
                aL[mt][3] = aLs[(ks + tig + 4) * 132 + row + 8];
            }
#pragma unroll
            for (int nt = 0; nt < 4; nt++) {
                int col = wn + nt * 8 + g;
                bH[nt][0] = bHs[(ks + tig) * 132 + col];
                bH[nt][1] = bHs[(ks + tig + 4) * 132 + col];
                bL[nt][0] = bLs[(ks + tig) * 132 + col];
                bL[nt][1] = bLs[(ks + tig + 4) * 132 + col];
            }
#pragma unroll
            for (int mt = 0; mt < 4; mt++)
#pragma unroll
                for (int nt = 0; nt < 4; nt++) {
                    mma_tf32(acc[mt][nt], aL[mt], bH[nt]);
                    mma_tf32(acc[mt][nt], aH[mt], bL[nt]);
                    mma_tf32(acc[mt][nt], aH[mt], bH[nt]);
                }
        }

        if (more)
            gemm_store_stage(AsH, AsL, BsH, BsL, cur ^ 1,
                             av0, av1, bv0, bv1, arow, ak4, bk, bn);
        __syncthreads();
    }

#pragma unroll
    for (int nt = 0; nt < 4; nt++) {
        int col = n0 + wn + nt * 8 + 2 * tig;
        float b0 = bias[col];
        float b1 = bias[col + 1];
#pragma unroll
        for (int mt = 0; mt < 4; mt++) {
            int row0 = m0 + wm + mt * 16 + g;
            float2 v0 = make_float2((acc[mt][nt][0] + b0) * alpha,
                                    (acc[mt][nt][1] + b1) * alpha);
            float2 v1 = make_float2((acc[mt][nt][2] + b0) * alpha,
                                    (acc[mt][nt][3] + b1) * alpha);
            *(float2*)&C[row0 * N + col]       = v0;
            *(float2*)&C[(row0 + 8) * N + col] = v1;
        }
    }
}

// Fused Q/K/V projection: blockIdx.z in {0,1,2} selects the GEMM.
__global__ __launch_bounds__(256)
void qkv_proj(const float* __restrict__ query, const float* __restrict__ key,
              const float* __restrict__ value,
              const float* __restrict__ Wq, const float* __restrict__ Wk,
              const float* __restrict__ Wv,
              const float* __restrict__ bq, const float* __restrict__ bk,
              const float* __restrict__ bv,
              float* __restrict__ oq, float* __restrict__ ok,
              float* __restrict__ ov, float qscale)
{
    const int z = blockIdx.z;
    const float* A    = (z == 0) ? query : (z == 1) ? key : value;
    const float* W    = (z == 0) ? Wq    : (z == 1) ? Wk  : Wv;
    const float* bias = (z == 0) ? bq    : (z == 1) ? bk  : bv;
    float*       C    = (z == 0) ? oq    : (z == 1) ? ok  : ov;
    float alpha       = (z == 0) ? qscale : 1.0f;
    sgemm_body(A, W, bias, C, alpha, BB * TT, DD, DD);
}

// Output projection (single GEMM).
__global__ __launch_bounds__(256)
void out_proj(const float* __restrict__ A, const float* __restrict__ W,
              const float* __restrict__ bias, float* __restrict__ C)
{
    sgemm_body(A, W, bias, C, 1.0f, BB * TT, DD, DD);
}

// ---------------------------------------------------------------------------
// Flash attention with split-tf32 mma (fp32-accurate).
// Per CTA: (b, h, 128-query tile). 8 warps; warp w owns q rows [w*16, w*16+16)
// and ALL keys -> softmax is warp-local. Stream over S in 64-key tiles.
// K/V split hi/lo once at tile-load, stored interleaved uint2 (LDS.64 per
// fragment pair). Q kept fp32 in regs (32 regs), split inline per tile —
// frees 32 regs so __launch_bounds__(256,2) holds <=128 regs -> 2 CTAs/SM.
// smem: Ks2/Vs2 [64][68] uint2, Ps [128][68] float.  (~102 KB)
// ---------------------------------------------------------------------------
#define Bb_R 128
#define Bb_C 64
#define SSTR 68
#define ATTN_SMEM ((4 * Bb_C * SSTR + Bb_R * SSTR) * 4)

__global__ __launch_bounds__(256, 2)
void attn_mma(const float* __restrict__ q, const float* __restrict__ k,
              const float* __restrict__ v, float* __restrict__ o)
{
    extern __shared__ unsigned smu[];
    uint2* Ks2 = (uint2*)smu;                 // [64][SSTR] (key, dk) {hi,lo}
    uint2* Vs2 = Ks2 + Bb_C * SSTR;           // [64][SSTR] (key, dk) {hi,lo}
    float* Ps  = (float*)(Vs2 + Bb_C * SSTR); // [128][SSTR] (qrow, key)

    const int tid  = threadIdx.x;
    const int lane = tid & 31;
    const int w    = tid >> 5;
    const int g    = lane >> 2;
    const int tig  = lane & 3;
    const int b    = blockIdx.z;
    const int h    = blockIdx.y;
    const int t0   = blockIdx.x * Bb_R;
    const int r0   = w * 16 + g;       // q row (within tile) for a0/a2,c0/c1
    const int r1   = r0 + 8;           // for a1/a3,c2/c3

    // ---- Load Q fragments once (fp32; split inline in the QK loop)
    float Qf[8][4];
    {
        const float* qb = q + (size_t)(b * TT + t0) * DD + h * DK;
#pragma unroll
        for (int ks = 0; ks < 8; ks++) {
            Qf[ks][0] = qb[r0 * DD + ks * 8 + tig];
            Qf[ks][1] = qb[r1 * DD + ks * 8 + tig];
            Qf[ks][2] = qb[r0 * DD + ks * 8 + tig + 4];
            Qf[ks][3] = qb[r1 * DD + ks * 8 + tig + 4];
        }
    }

    float O[8][4];
#pragma unroll
    for (int nt = 0; nt < 8; nt++)
#pragma unroll
        for (int i = 0; i < 4; i++) O[nt][i] = 0.0f;
    float m0_ = -INFINITY, m1_ = -INFINITY, l0_ = 0.0f, l1_ = 0.0f;

    const float* kb = k + (size_t)b * SS * DD + h * DK;
    const float* vb = v + (size_t)b * SS * DD + h * DK;

    for (int s0 = 0; s0 < SS; s0 += Bb_C) {
        __syncthreads();   // prior iter's PV reads of Ps/Vs done

        // ---- Load K,V tiles; split hi/lo once, store interleaved uint2
#pragma unroll
        for (int u = 0; u < 4; u++) {
            int idx = tid + u * 256;       // 0..1023
            int row = idx >> 4;            // 0..63
            int c4  = (idx & 15) * 4;      // 0..60
            float4 kv = *(const float4*)&kb[(size_t)(s0 + row) * DD + c4];
            float4 vv = *(const float4*)&vb[(size_t)(s0 + row) * DD + c4];
            uint4 kh, kl, vh, vl;
            split_tf32(kv.x, kh.x, kl.x); split_tf32(kv.y, kh.y, kl.y);
            split_tf32(kv.z, kh.z, kl.z); split_tf32(kv.w, kh.w, kl.w);
            split_tf32(vv.x, vh.x, vl.x); split_tf32(vv.y, vh.y, vl.y);
            split_tf32(vv.z, vh.z, vl.z); split_tf32(vv.w, vh.w, vl.w);
            *(uint4*)&Ks2[row * SSTR + c4]     = make_uint4(kh.x, kl.x, kh.y, kl.y);
            *(uint4*)&Ks2[row * SSTR + c4 + 2] = make_uint4(kh.z, kl.z, kh.w, kl.w);
            *(uint4*)&Vs2[row * SSTR + c4]     = make_uint4(vh.x, vl.x, vh.y, vl.y);
            *(uint4*)&Vs2[row * SSTR + c4 + 2] = make_uint4(vh.z, vl.z, vh.w, vl.w);
        }
        __syncthreads();

        // ---- Scores S = Q K^T (split-3). B-frag b0=(k=tig,n=g): Ks[n][k].
        float S[8][4];
#pragma unroll
        for (int nt = 0; nt < 8; nt++)
#pragma unroll
            for (int i = 0; i < 4; i++) S[nt][i] = 0.0f;

#pragma unroll
        for (int ks = 0; ks < 8; ks++) {
            unsigned qH[4], qL[4];
            split_tf32(Qf[ks][0], qH[0], qL[0]);
            split_tf32(Qf[ks][1], qH[1], qL[1]);
            split_tf32(Qf[ks][2], qH[2], qL[2]);
            split_tf32(Qf[ks][3], qH[3], qL[3]);
#pragma unroll
            for (int nt = 0; nt < 8; nt++) {
                int i0 = (nt * 8 + g) * SSTR + ks * 8 + tig;
                uint2 p0 = Ks2[i0];          // {hi, lo} one LDS.64
                uint2 p1 = Ks2[i0 + 4];
                unsigned bH[2] = {p0.x, p1.x};
                unsigned bL[2] = {p0.y, p1.y};
                mma_tf32(S[nt], qL, bH);
                mma_tf32(S[nt], qH, bL);
                mma_tf32(S[nt], qH, bH);
            }
        }

        // ---- Online softmax (warp-local; rows r0 and r1)
        float mx0 = -INFINITY, mx1 = -INFINITY;
#pragma unroll
        for (int nt = 0; nt < 8; nt++) {
            mx0 = fmaxf(mx0, fmaxf(S[nt][0], S[nt][1]));
            mx1 = fmaxf(mx1, fmaxf(S[nt][2], S[nt][3]));
        }
        mx0 = fmaxf(mx0, __shfl_xor_sync(0xffffffffu, mx0, 1));
        mx0 = fmaxf(mx0, __shfl_xor_sync(0xffffffffu, mx0, 2));
        mx1 = fmaxf(mx1, __shfl_xor_sync(0xffffffffu, mx1, 1));
        mx1 = fmaxf(mx1, __shfl_xor_sync(0xffffffffu, mx1, 2));

        float mn0 = fmaxf(m0_, mx0);
        float mn1 = fmaxf(m1_, mx1);
        float rs0 = 0.0f, rs1 = 0.0f;
#pragma unroll
        for (int nt = 0; nt < 8; nt++) {
            S[nt][0] = __expf(S[nt][0] - mn0);
            S[nt][1] = __expf(S[nt][1] - mn0);
            S[nt][2] = __expf(S[nt][2] - mn1);
            S[nt][3] = __expf(S[nt][3] - mn1);
            rs0 += S[nt][0] + S[nt][1];
            rs1 += S[nt][2] + S[nt][3];
        }
        rs0 += __shfl_xor_sync(0xffffffffu, rs0, 1);
        rs0 += __shfl_xor_sync(0xffffffffu, rs0, 2);
        rs1 += __shfl_xor_sync(0xffffffffu, rs1, 1);
        rs1 += __shfl_xor_sync(0xffffffffu, rs1, 2);

        float al0 = __expf(m0_ - mn0);
        float al1 = __expf(m1_ - mn1);
        l0_ = l0_ * al0 + rs0;  m0_ = mn0;
        l1_ = l1_ * al1 + rs1;  m1_ = mn1;
#pragma unroll
        for (int nt = 0; nt < 8; nt++) {
            O[nt][0] *= al0;  O[nt][1] *= al0;
            O[nt][2] *= al1;  O[nt][3] *= al1;
        }

        // ---- Store P (C-frag layout: cols nt*8 + 2*tig)
#pragma unroll
        for (int nt = 0; nt < 8; nt++) {
            *(float2*)&Ps[r0 * SSTR + nt * 8 + 2 * tig] = make_float2(S[nt][0], S[nt][1]);
            *(float2*)&Ps[r1 * SSTR + nt * 8 + 2 * tig] = make_float2(S[nt][2], S[nt][3]);
        }
        __syncthreads();

        // ---- O += P @ V (split-3). A from Ps (split at read), B from Vs2.
#pragma unroll
        for (int ks = 0; ks < 8; ks++) {
            unsigned aH[4], aL[4];
            split_tf32(Ps[r0 * SSTR + ks * 8 + tig],     aH[0], aL[0]);
            split_tf32(Ps[r1 * SSTR + ks * 8 + tig],     aH[1], aL[1]);
            split_tf32(Ps[r0 * SSTR + ks * 8 + tig + 4], aH[2], aL[2]);
            split_tf32(Ps[r1 * SSTR + ks * 8 + tig + 4], aH[3], aL[3]);
#pragma unroll
            for (int nt = 0; nt < 8; nt++) {
                uint2 p0 = Vs2[(ks * 8 + tig) * SSTR + nt * 8 + g];
                uint2 p1 = Vs2[(ks * 8 + tig + 4) * SSTR + nt * 8 + g];
                unsigned bH[2] = {p0.x, p1.x};
                unsigned bL[2] = {p0.y, p1.y};
                mma_tf32(O[nt], aL, bH);
                mma_tf32(O[nt], aH, bL);
                mma_tf32(O[nt], aH, bH);
            }
        }
    }

    // ---- Normalize and store
    float inv0 = 1.0f / l0_;
    float inv1 = 1.0f / l1_;
    float* ob = o + (size_t)(b * TT + t0) * DD + h * DK;
#pragma unroll
    for (int nt = 0; nt < 8; nt++) {
        *(float2*)&ob[r0 * DD + nt * 8 + 2 * tig] =
            make_float2(O[nt][0] * inv0, O[nt][1] * inv0);
        *(float2*)&ob[r1 * DD + nt * 8 + 2 * tig] =
            make_float2(O[nt][2] * inv1, O[nt][3] * inv1);
    }
}

// ---------------------------------------------------------------------------
// Launch.  Input order: query, value, key, Wq, bq, Wk, bk, Wv, bv, Wo, bo
// ---------------------------------------------------------------------------
extern "C" void kernel_launch(void* const* d_in, const int* in_sizes, int n_in,
                              void* d_out, int out_size)
{
    const float* query = (const float*)d_in[0];
    const float* value = (const float*)d_in[1];
    const float* key   = (const float*)d_in[2];
    const float* Wq    = (const float*)d_in[3];
    const float* bq    = (const float*)d_in[4];
    const float* Wk    = (const float*)d_in[5];
    const float* bk    = (const float*)d_in[6];
    const float* Wv    = (const float*)d_in[7];
    const float* bv    = (const float*)d_in[8];
    const float* Wo    = (const float*)d_in[9];
    const float* bo    = (const float*)d_in[10];
    float* out = (float*)d_out;

    float* dq; cudaGetSymbolAddress((void**)&dq, g_q);
    float* dk; cudaGetSymbolAddress((void**)&dk, g_k);
    float* dv; cudaGetSymbolAddress((void**)&dv, g_v);
    float* da; cudaGetSymbolAddress((void**)&da, g_attn);

    cudaFuncSetAttribute(attn_mma, cudaFuncAttributeMaxDynamicSharedMemorySize,
                         ATTN_SMEM);
    cudaFuncSetAttribute(qkv_proj, cudaFuncAttributeMaxDynamicSharedMemorySize,
                         GEMM_SMEM);
    cudaFuncSetAttribute(out_proj, cudaFuncAttributeMaxDynamicSharedMemorySize,
                         GEMM_SMEM);

    const float qscale = 0.125f;  // 1/sqrt(DK=64)
    dim3 gblk(256);

    // Fused Q/K/V projections: one 768-CTA launch (z selects the GEMM)
    dim3 qkvgrid(DD / 128, (BB * TT) / 128, 3);
    qkv_proj<<<qkvgrid, gblk, GEMM_SMEM>>>(query, key, value, Wq, Wk, Wv,
                                           bq, bk, bv, dq, dk, dv, qscale);

    // Attention
    dim3 agrid(TT / Bb_R, HH, BB);
    attn_mma<<<agrid, 256, ATTN_SMEM>>>(dq, dk, dv, da);

    // Output projection
    dim3 ogrid(DD / 128, (BB * TT) / 128);
    out_proj<<<ogrid, gblk, GEMM_SMEM>>>(da, Wo, bo, out);
}